// round 15
// baseline (speedup 1.0000x reference)
#include <cuda_runtime.h>
#include <math.h>

// ---------------- problem constants ----------------
#define BATCH 64
#define TDEC  150
#define NVOC  48
#define LHID  256
#define SHID  512
#define NMLP  128

typedef unsigned long long ull;

// ---------------- device scratch ----------------
__device__ float g_xw0[64*1024*1024];
__device__ float g_xw1[64*1024*1024];
__device__ float g_out0[64*1024*512];
__device__ float g_out1[64*512*512];
__device__ float g_feats[64*256*512];
__device__ float g_cf[64*256*128];
__device__ float g_h[2*2*256*64];          // [parity][dir][unit][batch]  (coalesced exchange)
__device__ float g_c[2*64*256];
__device__ float g_dh[2*64*512];
__device__ float g_ctx[64*512];
__device__ float g_phiWt[512*128];
__device__ unsigned g_barE[2];             // per-direction encoder barriers
__device__ unsigned g_barD;                // decoder barrier

// ---------------- split-phase grid barrier (proven primitives) ----------
__device__ __forceinline__ void gbar_arrive(unsigned* ctr)
{
    __syncthreads();
    if (threadIdx.x == 0) {
        asm volatile("red.release.gpu.global.add.u32 [%0], %1;"
                     :: "l"(ctr), "r"(1u) : "memory");
    }
}
__device__ __forceinline__ void gbar_wait(unsigned* ctr, unsigned& epoch, unsigned nb)
{
    if (threadIdx.x == 0) {
        unsigned target = epoch + nb;
        unsigned v;
        int spins = 0;
        for (;;) {
            asm volatile("ld.acquire.gpu.global.u32 %0, [%1];"
                         : "=r"(v) : "l"(ctr) : "memory");
            if (v >= target) break;
            if (++spins > 4) __nanosleep(64);
        }
    }
    epoch += nb;
    __syncthreads();
}
__device__ __forceinline__ void gbar(unsigned* ctr, unsigned& epoch, unsigned nb)
{
    gbar_arrive(ctr);
    gbar_wait(ctr, epoch, nb);
}

// ---------------- packed fp32x2 FMA (SASS FFMA2) ----------------
__device__ __forceinline__ void fma2(ull& d, ull a, ull b)
{
    asm("fma.rn.f32x2 %0, %1, %2, %0;" : "+l"(d) : "l"(a), "l"(b));
}

union UP { float4 f; ull u[2]; };
union U2 { ull u; float2 f; };

// ---------------- barrier reset ----------------
__global__ void reset_bars() {
    if (threadIdx.x == 0 && blockIdx.x == 0) {
        g_barE[0] = 0; g_barE[1] = 0; g_barD = 0;
    }
}

// ---------------- fp32 GEMM, software-pipelined (R14-proven) ---------------
__global__ __launch_bounds__(256) void gemm_bias(
    const float* __restrict__ A, const float* __restrict__ W,
    const float* __restrict__ bias, float* __restrict__ C,
    int M, int N, int K, int relu, int gate_perm)
{
    __shared__ float As[2][16 * 132];
    __shared__ float Ws[2][16 * 68];
    int bm = blockIdx.y << 7, bn = blockIdx.x << 6;
    int tid = threadIdx.x;
    int ty = tid >> 4, tx = tid & 15;
    const float* Ap = A + (size_t)bm * K;

    int ar0 = tid >> 2, ac = (tid & 3) << 2;
    int ar1 = ar0 + 64;
    int nprime = bn + ar0;
    int nrow = gate_perm ? ((nprime & 3) * 256 + (nprime >> 2)) : nprime;
    const float* ApRow0 = Ap + (size_t)ar0 * K;
    const float* ApRow1 = Ap + (size_t)ar1 * K;
    const float* WpRow  = W + (size_t)nrow * K;

    float acc[8][4];
#pragma unroll
    for (int i = 0; i < 8; i++)
#pragma unroll
        for (int j = 0; j < 4; j++) acc[i][j] = 0.f;

    float4 ra0 = *(const float4*)&ApRow0[ac];
    float4 ra1 = *(const float4*)&ApRow1[ac];
    float4 rw  = *(const float4*)&WpRow[ac];
    {
        As[0][(ac + 0) * 132 + ar0] = ra0.x;
        As[0][(ac + 1) * 132 + ar0] = ra0.y;
        As[0][(ac + 2) * 132 + ar0] = ra0.z;
        As[0][(ac + 3) * 132 + ar0] = ra0.w;
        As[0][(ac + 0) * 132 + ar1] = ra1.x;
        As[0][(ac + 1) * 132 + ar1] = ra1.y;
        As[0][(ac + 2) * 132 + ar1] = ra1.z;
        As[0][(ac + 3) * 132 + ar1] = ra1.w;
        Ws[0][(ac + 0) * 68 + ar0] = rw.x;
        Ws[0][(ac + 1) * 68 + ar0] = rw.y;
        Ws[0][(ac + 2) * 68 + ar0] = rw.z;
        Ws[0][(ac + 3) * 68 + ar0] = rw.w;
    }
    __syncthreads();

    int buf = 0;
    for (int k0 = 0; k0 < K; k0 += 16) {
        int more = (k0 + 16 < K);
        if (more) {
            ra0 = *(const float4*)&ApRow0[k0 + 16 + ac];
            ra1 = *(const float4*)&ApRow1[k0 + 16 + ac];
            rw  = *(const float4*)&WpRow[k0 + 16 + ac];
        }
        const float* Ab = As[buf];
        const float* Wb = Ws[buf];
#pragma unroll
        for (int kk = 0; kk < 16; kk++) {
            float4 a0 = *(const float4*)&Ab[kk * 132 + ty * 8];
            float4 a1 = *(const float4*)&Ab[kk * 132 + ty * 8 + 4];
            float4 w  = *(const float4*)&Wb[kk * 68 + tx * 4];
            acc[0][0] += a0.x * w.x; acc[0][1] += a0.x * w.y; acc[0][2] += a0.x * w.z; acc[0][3] += a0.x * w.w;
            acc[1][0] += a0.y * w.x; acc[1][1] += a0.y * w.y; acc[1][2] += a0.y * w.z; acc[1][3] += a0.y * w.w;
            acc[2][0] += a0.z * w.x; acc[2][1] += a0.z * w.y; acc[2][2] += a0.z * w.z; acc[2][3] += a0.z * w.w;
            acc[3][0] += a0.w * w.x; acc[3][1] += a0.w * w.y; acc[3][2] += a0.w * w.z; acc[3][3] += a0.w * w.w;
            acc[4][0] += a1.x * w.x; acc[4][1] += a1.x * w.y; acc[4][2] += a1.x * w.z; acc[4][3] += a1.x * w.w;
            acc[5][0] += a1.y * w.x; acc[5][1] += a1.y * w.y; acc[5][2] += a1.y * w.z; acc[5][3] += a1.y * w.w;
            acc[6][0] += a1.z * w.x; acc[6][1] += a1.z * w.y; acc[6][2] += a1.z * w.z; acc[6][3] += a1.z * w.w;
            acc[7][0] += a1.w * w.x; acc[7][1] += a1.w * w.y; acc[7][2] += a1.w * w.z; acc[7][3] += a1.w * w.w;
        }
        if (more) {
            int nb2 = buf ^ 1;
            As[nb2][(ac + 0) * 132 + ar0] = ra0.x;
            As[nb2][(ac + 1) * 132 + ar0] = ra0.y;
            As[nb2][(ac + 2) * 132 + ar0] = ra0.z;
            As[nb2][(ac + 3) * 132 + ar0] = ra0.w;
            As[nb2][(ac + 0) * 132 + ar1] = ra1.x;
            As[nb2][(ac + 1) * 132 + ar1] = ra1.y;
            As[nb2][(ac + 2) * 132 + ar1] = ra1.z;
            As[nb2][(ac + 3) * 132 + ar1] = ra1.w;
            Ws[nb2][(ac + 0) * 68 + ar0] = rw.x;
            Ws[nb2][(ac + 1) * 68 + ar0] = rw.y;
            Ws[nb2][(ac + 2) * 68 + ar0] = rw.z;
            Ws[nb2][(ac + 3) * 68 + ar0] = rw.w;
            __syncthreads();
            buf = nb2;
        }
    }
    float bvx, bvy, bvz, bvw;
    if (gate_perm) {
        int n0 = bn + tx * 4;
        bvx = bias[((n0 + 0) & 3) * 256 + ((n0 + 0) >> 2)];
        bvy = bias[((n0 + 1) & 3) * 256 + ((n0 + 1) >> 2)];
        bvz = bias[((n0 + 2) & 3) * 256 + ((n0 + 2) >> 2)];
        bvw = bias[((n0 + 3) & 3) * 256 + ((n0 + 3) >> 2)];
    } else {
        float4 bv = *(const float4*)&bias[bn + tx * 4];
        bvx = bv.x; bvy = bv.y; bvz = bv.z; bvw = bv.w;
    }
#pragma unroll
    for (int i = 0; i < 8; i++) {
        int m = bm + ty * 8 + i;
        float4 o;
        o.x = acc[i][0] + bvx; o.y = acc[i][1] + bvy;
        o.z = acc[i][2] + bvz; o.w = acc[i][3] + bvw;
        if (relu) {
            o.x = fmaxf(o.x, 0.f); o.y = fmaxf(o.y, 0.f);
            o.z = fmaxf(o.z, 0.f); o.w = fmaxf(o.w, 0.f);
        }
        *(float4*)&C[(size_t)m * N + bn + tx * 4] = o;
    }
}

// ---------------- persistent encoder scan: coalesced h exchange ------------
// 512 threads; warp map: kh = wrp>>3, u = (wrp>>1)&3, bh = wrp&1; lane = batch.
// g_h is [parity][dir][unit][batch]: producer stores are 128B-coalesced per
// warp; consumer fill is coalesced load + straight-through STS (no transpose).
// smem h = [unit 256][batch pitch 68]; inner loop h reads are LDS.32,
// conflict-free (lanes = consecutive batches).
#define ENC_SMEM ((16 * 264 + 256 * 68 + 256 * 4) * 4)
__global__ __launch_bounds__(512) void enc_scan(
    const float* __restrict__ xw_f, const float* __restrict__ xw_b,
    const float* __restrict__ whh_f, const float* __restrict__ whh_b,
    float* __restrict__ out, int Tl, unsigned epoch0)
{
    extern __shared__ float smem[];
    float* sh_w = smem;               // 16 x 256 (pitch 264)
    float* sh_x = smem + 16 * 264;    // 256 units x 64 batches (pitch 68)
    float* sh_p = sh_x + 256 * 68;    // 256 x 4 partials (kh=1 -> kh=0)

    int tid = threadIdx.x;
    int lane = tid & 31, wrp = tid >> 5;
    int kh = wrp >> 3;
    int u = (wrp >> 1) & 3;
    int bh = wrp & 1;
    int b = bh * 32 + lane;
    int dir = blockIdx.y;
    int hu0 = blockIdx.x << 2;
    int hu = hu0 + u;
    unsigned epoch = epoch0;
    const unsigned nb = gridDim.x;
    unsigned* ctr = &g_barE[dir];

    const float* xw  = dir ? xw_b  : xw_f;
    const float* Whh = dir ? whh_b : whh_f;

    for (int i = tid; i < 16 * 64; i += 512) {
        int r = i >> 6, kq = (i & 63) << 2;
        int grow = ((r >> 2) << 8) + hu0 + (r & 3);
        *(float4*)&sh_w[r * 264 + kq] = *(const float4*)&Whh[(size_t)grow * 256 + kq];
    }

    float creg = 0.f;
    if (kh == 0)
        __stcg(&g_h[(size_t)((0 * 2 + dir) * 256 + hu) * 64 + b], 0.f);
    gbar(ctr, epoch, nb);

    const float* wr0 = &sh_w[(0 * 4 + u) * 264];
    const float* wr1 = &sh_w[(1 * 4 + u) * 264];
    const float* wr2 = &sh_w[(2 * 4 + u) * 264];
    const float* wr3 = &sh_w[(3 * 4 + u) * 264];
    float* pp = &sh_p[(u * 64 + b) * 4];

    float4 xg = make_float4(0.f, 0.f, 0.f, 0.f);
    if (kh == 0) {
        int tt0 = dir ? (Tl - 1) : 0;
        xg = __ldg((const float4*)&xw[((size_t)b * Tl + tt0) * 1024 + (hu << 2)]);
    }

    for (int t = 0; t < Tl; t++) {
        int tt = dir ? (Tl - 1 - t) : t;
        int pin = t & 1, pout = pin ^ 1;
        const float* hin = g_h + (size_t)(pin * 2 + dir) * 256 * 64;

        // coalesced fill: [unit][batch] -> [unit][batch+pad], no transpose
        for (int i = tid; i < 4096; i += 512) {
            int un = i >> 3, q = (i & 7) << 3;       // 8 float8?? -> use float4: q in 0..60
            // i indexes 4096 float4s: unit = i>>4, quad = i&15
            (void)un; (void)q;
        }
#pragma unroll
        for (int it = 0; it < 8; it++) {
            int i = tid + it * 512;                  // 0..4095 float4 index
            int un = i >> 4, q = (i & 15) << 2;      // unit row, float offset
            *(float4*)&sh_x[un * 68 + q] = __ldcg((const float4*)&hin[un * 64 + q]);
        }
        __syncthreads();

        ull A0 = 0ull, A1 = 0ull, A2 = 0ull, A3 = 0ull;
#pragma unroll 8
        for (int kk = kh * 128; kk < kh * 128 + 128; kk += 4) {
            U2 hA, hB;
            hA.f = make_float2(sh_x[(kk + 0) * 68 + b], sh_x[(kk + 1) * 68 + b]);
            hB.f = make_float2(sh_x[(kk + 2) * 68 + b], sh_x[(kk + 3) * 68 + b]);
            UP w0, w1, w2, w3;
            w0.f = *(const float4*)&wr0[kk];
            w1.f = *(const float4*)&wr1[kk];
            w2.f = *(const float4*)&wr2[kk];
            w3.f = *(const float4*)&wr3[kk];
            fma2(A0, hA.u, w0.u[0]); fma2(A1, hA.u, w1.u[0]);
            fma2(A2, hA.u, w2.u[0]); fma2(A3, hA.u, w3.u[0]);
            fma2(A0, hB.u, w0.u[1]); fma2(A1, hB.u, w1.u[1]);
            fma2(A2, hB.u, w2.u[1]); fma2(A3, hB.u, w3.u[1]);
        }
        U2 r0, r1, r2, r3;
        r0.u = A0; r1.u = A1; r2.u = A2; r3.u = A3;
        if (kh == 1) {
            *(float4*)pp = make_float4(r0.f.x + r0.f.y, r1.f.x + r1.f.y,
                                       r2.f.x + r2.f.y, r3.f.x + r3.f.y);
        }
        __syncthreads();

        float hn = 0.f;
        if (kh == 0) {
            float4 p = *(const float4*)pp;
            float zi = r0.f.x + r0.f.y + p.x + xg.x;
            float zf = r1.f.x + r1.f.y + p.y + xg.y;
            float zg = r2.f.x + r2.f.y + p.z + xg.z;
            float zo = r3.f.x + r3.f.y + p.w + xg.w;
            float si = 1.f / (1.f + expf(-zi));
            float sf = 1.f / (1.f + expf(-zf));
            float so = 1.f / (1.f + expf(-zo));
            float cn = sf * creg + si * tanhf(zg);
            hn = so * tanhf(cn);
            creg = cn;
            // coalesced publish: one 128B line per warp
            __stcg(&g_h[(size_t)((pout * 2 + dir) * 256 + hu) * 64 + b], hn);
        }

        gbar_arrive(ctr);
        if (kh == 0) {
            out[((size_t)b * Tl + tt) * 512 + dir * 256 + hu] = hn;
            if (t + 1 < Tl) {
                int tn = dir ? (Tl - 2 - t) : (t + 1);
                xg = __ldg((const float4*)&xw[((size_t)b * Tl + tn) * 1024 + (hu << 2)]);
            }
        }
        gbar_wait(ctr, epoch, nb);
    }
    if (kh == 0)
        g_c[(size_t)(dir * 64 + b) * 256 + hu] = creg;
}

// ---------------- persistent decoder (R13/R14-proven) ----------------
#define DEC_SMEM ((16 * 1032 + 64 * 516 + 512 + 128 + 256 + 512 + 64 + 256) * 4)
__global__ __launch_bounds__(256) void dec_scan(
    const float* __restrict__ sWih, const float* __restrict__ sWhh,
    const float* __restrict__ sb, const int* __restrict__ gt,
    const float* __restrict__ phi_b,
    const float* __restrict__ fcW, const float* __restrict__ fcb,
    float* __restrict__ out_lps)
{
    extern __shared__ float smem[];
    float* sh_w  = smem;
    float* sh_x  = sh_w + 16 * 1032;
    float* sh_h  = sh_x + 64 * 516;
    float* sh_q  = sh_h + 512;
    float* sh_e  = sh_q + 128;
    float* sh_c2 = sh_e + 256;
    float* sh_l  = sh_c2 + 512;
    float* sr    = sh_l + 64;

    int tid = threadIdx.x;
    int lane = tid & 31, wrp = tid >> 5;
    int u = wrp & 3, bh = wrp >> 2;
    int b = bh * 32 + lane;
    int hu0 = blockIdx.x << 2;
    int hu = hu0 + u;
    unsigned epoch = 0;
    const unsigned nb = gridDim.x;
    unsigned* ctr = &g_barD;

    for (int i = tid; i < 16 * 256; i += 256) {
        int r = i >> 8, kq = (i & 255) << 2;
        int grow = (r >> 2) * SHID + hu0 + (r & 3);
        float4 v;
        if (kq < 512) v = *(const float4*)&sWih[(size_t)grow * 560 + 48 + kq];
        else          v = *(const float4*)&sWhh[(size_t)grow * 512 + (kq - 512)];
        *(float4*)&sh_w[r * 1032 + kq] = v;
    }

    float creg = 0.f;
    __stcg(&g_dh[(size_t)b * 512 + hu], 0.f);
    __stcg(&g_ctx[(size_t)b * 512 + hu], __ldg(&g_feats[(size_t)b * 256 * 512 + hu]));
    gbar(ctr, epoch, nb);

    float bi0 = sb[0 * SHID + hu], bi1 = sb[1 * SHID + hu];
    float bi2 = sb[2 * SHID + hu], bi3 = sb[3 * SHID + hu];

    for (int t = 0; t < TDEC; t++) {
        int pin = t & 1, pout = pin ^ 1;
        int tok = (t == 0) ? 0 : gt[b * TDEC + (t - 1)];
        U2 A0, A1, A2, A3;
        A0.f = make_float2(sWih[(size_t)(0 * SHID + hu) * 560 + tok] + bi0, 0.f);
        A1.f = make_float2(sWih[(size_t)(1 * SHID + hu) * 560 + tok] + bi1, 0.f);
        A2.f = make_float2(sWih[(size_t)(2 * SHID + hu) * 560 + tok] + bi2, 0.f);
        A3.f = make_float2(sWih[(size_t)(3 * SHID + hu) * 560 + tok] + bi3, 0.f);

        const float* hin = g_dh + (size_t)pin * 64 * 512;
#pragma unroll
        for (int c = 0; c < 2; c++) {
            __syncthreads();
            const float* src = (c == 0) ? g_ctx : hin;
            for (int i = tid; i < 64 * 128; i += 256) {
                int bb = i >> 7, kq = (i & 127) << 2;
                *(float4*)&sh_x[bb * 516 + kq] = __ldcg((const float4*)&src[(size_t)bb * 512 + kq]);
            }
            __syncthreads();
            const float* w0p = &sh_w[(0 * 4 + u) * 1032 + c * 512];
            const float* w1p = &sh_w[(1 * 4 + u) * 1032 + c * 512];
            const float* w2p = &sh_w[(2 * 4 + u) * 1032 + c * 512];
            const float* w3p = &sh_w[(3 * 4 + u) * 1032 + c * 512];
            const float* hp  = &sh_x[b * 516];
#pragma unroll 8
            for (int kk = 0; kk < 512; kk += 4) {
                UP h, w0, w1, w2, w3;
                h.f  = *(const float4*)&hp[kk];
                w0.f = *(const float4*)&w0p[kk];
                w1.f = *(const float4*)&w1p[kk];
                w2.f = *(const float4*)&w2p[kk];
                w3.f = *(const float4*)&w3p[kk];
                fma2(A0.u, h.u[0], w0.u[0]); fma2(A1.u, h.u[0], w1.u[0]);
                fma2(A2.u, h.u[0], w2.u[0]); fma2(A3.u, h.u[0], w3.u[0]);
                fma2(A0.u, h.u[1], w0.u[1]); fma2(A1.u, h.u[1], w1.u[1]);
                fma2(A2.u, h.u[1], w2.u[1]); fma2(A3.u, h.u[1], w3.u[1]);
            }
        }
        float acc0 = A0.f.x + A0.f.y;
        float acc1 = A1.f.x + A1.f.y;
        float acc2 = A2.f.x + A2.f.y;
        float acc3 = A3.f.x + A3.f.y;
        float si = 1.f / (1.f + expf(-acc0));
        float sf = 1.f / (1.f + expf(-acc1));
        float so = 1.f / (1.f + expf(-acc3));
        float cn = sf * creg + si * tanhf(acc2);
        float hn = so * tanhf(cn);
        creg = cn;
        __stcg(&g_dh[(size_t)pout * 64 * 512 + b * 512 + hu], hn);
        gbar(ctr, epoch, nb);

        if (blockIdx.x < 64) {
            int bb = blockIdx.x;
            const float* h = g_dh + (size_t)pout * 64 * 512 + (size_t)bb * 512;
            for (int i = tid; i < 512; i += 256) sh_h[i] = __ldcg(&h[i]);
            __syncthreads();

            {
                int j = tid >> 1, hf = tid & 1;
                const float* pw = g_phiWt + (size_t)hf * 256 * 128;
                const float* hh = sh_h + hf * 256;
                float a0 = 0.f, a1 = 0.f, a2 = 0.f, a3 = 0.f;
                for (int k = 0; k < 256; k += 4) {
                    a0 += hh[k + 0] * pw[(k + 0) * 128 + j];
                    a1 += hh[k + 1] * pw[(k + 1) * 128 + j];
                    a2 += hh[k + 2] * pw[(k + 2) * 128 + j];
                    a3 += hh[k + 3] * pw[(k + 3) * 128 + j];
                }
                sr[tid] = a0 + a1 + a2 + a3;
            }
            __syncthreads();
            if (tid < 128) {
                float q = sr[2 * tid] + sr[2 * tid + 1] + phi_b[tid];
                sh_q[tid] = q > 0.f ? q : 0.f;
            }
            __syncthreads();

            {
                const float* cfp = g_cf + ((size_t)bb * 256 + tid) * 128;
                float a0 = 0.f, a1 = 0.f, a2 = 0.f, a3 = 0.f;
                for (int j = 0; j < 128; j += 4) {
                    a0 += sh_q[j + 0] * cfp[j + 0];
                    a1 += sh_q[j + 1] * cfp[j + 1];
                    a2 += sh_q[j + 2] * cfp[j + 2];
                    a3 += sh_q[j + 3] * cfp[j + 3];
                }
                sh_e[tid] = a0 + a1 + a2 + a3;
            }
            __syncthreads();

            float v = sh_e[tid];
            sr[tid] = v; __syncthreads();
            for (int s = 128; s > 0; s >>= 1) { if (tid < s) sr[tid] = fmaxf(sr[tid], sr[tid + s]); __syncthreads(); }
            float m = sr[0]; __syncthreads();
            float e = expf(v - m);
            sr[tid] = e; __syncthreads();
            for (int s = 128; s > 0; s >>= 1) { if (tid < s) sr[tid] += sr[tid + s]; __syncthreads(); }
            float inv = 1.f / sr[0];
            __syncthreads();
            sh_e[tid] = e * inv;
            __syncthreads();

            for (int d0 = 0; d0 < 512; d0 += 256) {
                int d = d0 + tid;
                const float* fp = g_feats + (size_t)bb * 256 * 512 + d;
                float a0 = 0.f, a1 = 0.f, a2 = 0.f, a3 = 0.f;
                for (int tt2 = 0; tt2 < 256; tt2 += 4) {
                    a0 += sh_e[tt2 + 0] * fp[(size_t)(tt2 + 0) * 512];
                    a1 += sh_e[tt2 + 1] * fp[(size_t)(tt2 + 1) * 512];
                    a2 += sh_e[tt2 + 2] * fp[(size_t)(tt2 + 2) * 512];
                    a3 += sh_e[tt2 + 3] * fp[(size_t)(tt2 + 3) * 512];
                }
                float cv = a0 + a1 + a2 + a3;
                sh_c2[d] = cv;
                __stcg(&g_ctx[(size_t)bb * 512 + d], cv);
            }
            __syncthreads();

            if (tid < 192) {
                int v2 = tid >> 2, part = tid & 3;
                const float* wr = fcW + (size_t)v2 * 1024 + part * 256;
                const float* src = (part < 2) ? (sh_h + part * 256) : (sh_c2 + (part - 2) * 256);
                float a0 = 0.f, a1 = 0.f, a2 = 0.f, a3 = 0.f;
                for (int k = 0; k < 256; k += 4) {
                    a0 += src[k + 0] * wr[k + 0];
                    a1 += src[k + 1] * wr[k + 1];
                    a2 += src[k + 2] * wr[k + 2];
                    a3 += src[k + 3] * wr[k + 3];
                }
                sr[tid] = a0 + a1 + a2 + a3;
            }
            __syncthreads();
            if (tid < 48) {
                sh_l[tid] = sr[tid * 4] + sr[tid * 4 + 1] + sr[tid * 4 + 2] + sr[tid * 4 + 3] + fcb[tid];
            }
            __syncthreads();
            if (tid < 48) {
                float m2 = -1e30f;
                for (int j = 0; j < 48; j++) m2 = fmaxf(m2, sh_l[j]);
                float s2 = 0.f;
                for (int j = 0; j < 48; j++) s2 += expf(sh_l[j] - m2);
                out_lps[(size_t)bb * TDEC * NVOC + (size_t)t * NVOC + tid] = sh_l[tid] - m2 - logf(s2);
            }
        }
        gbar(ctr, epoch, nb);
    }
}

// ---------------- small helpers ----------------
__global__ void transpose_phi(const float* __restrict__ W) {
    int j = blockIdx.x;
    for (int k = threadIdx.x; k < 512; k += 256) g_phiWt[k * 128 + j] = W[j * 512 + k];
}

__global__ void fin_hc(float* __restrict__ out) {
    int b = blockIdx.x;
    for (int i = threadIdx.x; i < 1024; i += 256) {
        int q = i >> 8, r = i & 255;
        float v;
        if (q == 0)      v = g_h[(size_t)((0 * 2 + 0) * 256 + r) * 64 + b];
        else if (q == 1) v = g_h[(size_t)((0 * 2 + 1) * 256 + r) * 64 + b];
        else if (q == 2) v = g_c[(size_t)(0 * 64 + b) * 256 + r];
        else             v = g_c[(size_t)(1 * 64 + b) * 256 + r];
        out[(size_t)b * 1024 + i] = v;
    }
}

// ---------------- host launcher ----------------
extern "C" void kernel_launch(void* const* d_in, const int* in_sizes, int n_in,
                              void* d_out, int out_size)
{
    const float* inputs = (const float*)d_in[0];
    const int*   gt     = (const int*)d_in[1];
    const float* W[27];
    for (int i = 0; i < 27; i++) W[i] = (const float*)d_in[i + 2];

    float *xw0, *xw1, *out0, *out1, *feats, *cf;
    cudaGetSymbolAddress((void**)&xw0, g_xw0);
    cudaGetSymbolAddress((void**)&xw1, g_xw1);
    cudaGetSymbolAddress((void**)&out0, g_out0);
    cudaGetSymbolAddress((void**)&out1, g_out1);
    cudaGetSymbolAddress((void**)&feats, g_feats);
    cudaGetSymbolAddress((void**)&cf, g_cf);

    cudaFuncSetAttribute(enc_scan, cudaFuncAttributeMaxDynamicSharedMemorySize, ENC_SMEM);
    cudaFuncSetAttribute(dec_scan, cudaFuncAttributeMaxDynamicSharedMemorySize, DEC_SMEM);

    float* dout = (float*)d_out;

    const float* A = inputs;
    float* outs[3] = {out0, out1, feats};
    int Tl = 1024, K = 160;
    unsigned ebase = 0;
    for (int l = 0; l < 3; l++) {
        int M = 64 * Tl;
        dim3 gg(1024 / 64, M / 128);
        gemm_bias<<<gg, 256>>>(A, W[l * 6 + 0], W[l * 6 + 2], xw0, M, 1024, K, 0, 1);
        gemm_bias<<<gg, 256>>>(A, W[l * 6 + 3], W[l * 6 + 5], xw1, M, 1024, K, 0, 1);
        if (l == 0) reset_bars<<<1, 32>>>();
        enc_scan<<<dim3(64, 2), 512, ENC_SMEM>>>(xw0, xw1, W[l * 6 + 1], W[l * 6 + 4],
                                                 outs[l], Tl, ebase);
        ebase += 64u * (unsigned)(Tl + 1);
        A = outs[l];
        Tl >>= 1;
        K = 1024;
    }

    // comp_feat = relu(feats @ psi_W^T + psi_b)   [16384,128]
    gemm_bias<<<dim3(2, 16384 / 128), 256>>>(feats, W[23], W[24], cf, 16384, 128, 512, 1, 0);
    transpose_phi<<<128, 256>>>(W[21]);
    fin_hc<<<64, 256>>>(dout + (size_t)BATCH * TDEC * NVOC);

    // ---------------- decoder ----------------
    dec_scan<<<128, 256, DEC_SMEM>>>(W[18], W[19], W[20], gt, W[22], W[25], W[26], dout);
}

// round 16
// speedup vs baseline: 1.0614x; 1.0614x over previous
#include <cuda_runtime.h>
#include <math.h>

// ---------------- problem constants ----------------
#define BATCH 64
#define TDEC  150
#define NVOC  48
#define LHID  256
#define SHID  512
#define NMLP  128

typedef unsigned long long ull;

// ---------------- device scratch ----------------
__device__ float g_xw0[64*1024*1024];
__device__ float g_xw1[64*1024*1024];
__device__ float g_out0[64*1024*512];
__device__ float g_out1[64*512*512];
__device__ float g_feats[64*256*512];
__device__ float g_cf[64*256*128];
__device__ float g_h[2*2*64*256];          // [parity][dir][b][256]
__device__ float g_c[2*64*256];
__device__ float g_dh[2*64*512];
__device__ float g_ctx[64*512];
__device__ float g_phiWt[512*128];
__device__ unsigned g_barE[2];             // per-direction encoder barriers
__device__ unsigned g_barD;                // decoder barrier

// ---------------- split-phase grid barrier (proven primitives) ----------
__device__ __forceinline__ void gbar_arrive(unsigned* ctr)
{
    __syncthreads();
    if (threadIdx.x == 0) {
        asm volatile("red.release.gpu.global.add.u32 [%0], %1;"
                     :: "l"(ctr), "r"(1u) : "memory");
    }
}
__device__ __forceinline__ void gbar_wait(unsigned* ctr, unsigned& epoch, unsigned nb)
{
    if (threadIdx.x == 0) {
        unsigned target = epoch + nb;
        unsigned v;
        int spins = 0;
        for (;;) {
            asm volatile("ld.acquire.gpu.global.u32 %0, [%1];"
                         : "=r"(v) : "l"(ctr) : "memory");
            if (v >= target) break;
            if (++spins > 16) __nanosleep(64);
        }
    }
    epoch += nb;
    __syncthreads();
}
__device__ __forceinline__ void gbar(unsigned* ctr, unsigned& epoch, unsigned nb)
{
    gbar_arrive(ctr);
    gbar_wait(ctr, epoch, nb);
}

// ---------------- packed fp32x2 FMA (SASS FFMA2) ----------------
__device__ __forceinline__ void fma2(ull& d, ull a, ull b)
{
    asm("fma.rn.f32x2 %0, %1, %2, %0;" : "+l"(d) : "l"(a), "l"(b));
}

union UP { float4 f; ull u[2]; };
union U2 { ull u; float2 f; };

// ---------------- barrier reset ----------------
__global__ void reset_bars() {
    if (threadIdx.x == 0 && blockIdx.x == 0) {
        g_barE[0] = 0; g_barE[1] = 0; g_barD = 0;
    }
}

// ---------------- fp32 GEMM, software-pipelined (R14-proven) ---------------
__global__ __launch_bounds__(256) void gemm_bias(
    const float* __restrict__ A, const float* __restrict__ W,
    const float* __restrict__ bias, float* __restrict__ C,
    int M, int N, int K, int relu, int gate_perm)
{
    __shared__ float As[2][16 * 132];
    __shared__ float Ws[2][16 * 68];
    int bm = blockIdx.y << 7, bn = blockIdx.x << 6;
    int tid = threadIdx.x;
    int ty = tid >> 4, tx = tid & 15;
    const float* Ap = A + (size_t)bm * K;

    int ar0 = tid >> 2, ac = (tid & 3) << 2;
    int ar1 = ar0 + 64;
    int nprime = bn + ar0;
    int nrow = gate_perm ? ((nprime & 3) * 256 + (nprime >> 2)) : nprime;
    const float* ApRow0 = Ap + (size_t)ar0 * K;
    const float* ApRow1 = Ap + (size_t)ar1 * K;
    const float* WpRow  = W + (size_t)nrow * K;

    float acc[8][4];
#pragma unroll
    for (int i = 0; i < 8; i++)
#pragma unroll
        for (int j = 0; j < 4; j++) acc[i][j] = 0.f;

    float4 ra0 = *(const float4*)&ApRow0[ac];
    float4 ra1 = *(const float4*)&ApRow1[ac];
    float4 rw  = *(const float4*)&WpRow[ac];
    {
        As[0][(ac + 0) * 132 + ar0] = ra0.x;
        As[0][(ac + 1) * 132 + ar0] = ra0.y;
        As[0][(ac + 2) * 132 + ar0] = ra0.z;
        As[0][(ac + 3) * 132 + ar0] = ra0.w;
        As[0][(ac + 0) * 132 + ar1] = ra1.x;
        As[0][(ac + 1) * 132 + ar1] = ra1.y;
        As[0][(ac + 2) * 132 + ar1] = ra1.z;
        As[0][(ac + 3) * 132 + ar1] = ra1.w;
        Ws[0][(ac + 0) * 68 + ar0] = rw.x;
        Ws[0][(ac + 1) * 68 + ar0] = rw.y;
        Ws[0][(ac + 2) * 68 + ar0] = rw.z;
        Ws[0][(ac + 3) * 68 + ar0] = rw.w;
    }
    __syncthreads();

    int buf = 0;
    for (int k0 = 0; k0 < K; k0 += 16) {
        int more = (k0 + 16 < K);
        if (more) {
            ra0 = *(const float4*)&ApRow0[k0 + 16 + ac];
            ra1 = *(const float4*)&ApRow1[k0 + 16 + ac];
            rw  = *(const float4*)&WpRow[k0 + 16 + ac];
        }
        const float* Ab = As[buf];
        const float* Wb = Ws[buf];
#pragma unroll
        for (int kk = 0; kk < 16; kk++) {
            float4 a0 = *(const float4*)&Ab[kk * 132 + ty * 8];
            float4 a1 = *(const float4*)&Ab[kk * 132 + ty * 8 + 4];
            float4 w  = *(const float4*)&Wb[kk * 68 + tx * 4];
            acc[0][0] += a0.x * w.x; acc[0][1] += a0.x * w.y; acc[0][2] += a0.x * w.z; acc[0][3] += a0.x * w.w;
            acc[1][0] += a0.y * w.x; acc[1][1] += a0.y * w.y; acc[1][2] += a0.y * w.z; acc[1][3] += a0.y * w.w;
            acc[2][0] += a0.z * w.x; acc[2][1] += a0.z * w.y; acc[2][2] += a0.z * w.z; acc[2][3] += a0.z * w.w;
            acc[3][0] += a0.w * w.x; acc[3][1] += a0.w * w.y; acc[3][2] += a0.w * w.z; acc[3][3] += a0.w * w.w;
            acc[4][0] += a1.x * w.x; acc[4][1] += a1.x * w.y; acc[4][2] += a1.x * w.z; acc[4][3] += a1.x * w.w;
            acc[5][0] += a1.y * w.x; acc[5][1] += a1.y * w.y; acc[5][2] += a1.y * w.z; acc[5][3] += a1.y * w.w;
            acc[6][0] += a1.z * w.x; acc[6][1] += a1.z * w.y; acc[6][2] += a1.z * w.z; acc[6][3] += a1.z * w.w;
            acc[7][0] += a1.w * w.x; acc[7][1] += a1.w * w.y; acc[7][2] += a1.w * w.z; acc[7][3] += a1.w * w.w;
        }
        if (more) {
            int nb2 = buf ^ 1;
            As[nb2][(ac + 0) * 132 + ar0] = ra0.x;
            As[nb2][(ac + 1) * 132 + ar0] = ra0.y;
            As[nb2][(ac + 2) * 132 + ar0] = ra0.z;
            As[nb2][(ac + 3) * 132 + ar0] = ra0.w;
            As[nb2][(ac + 0) * 132 + ar1] = ra1.x;
            As[nb2][(ac + 1) * 132 + ar1] = ra1.y;
            As[nb2][(ac + 2) * 132 + ar1] = ra1.z;
            As[nb2][(ac + 3) * 132 + ar1] = ra1.w;
            Ws[nb2][(ac + 0) * 68 + ar0] = rw.x;
            Ws[nb2][(ac + 1) * 68 + ar0] = rw.y;
            Ws[nb2][(ac + 2) * 68 + ar0] = rw.z;
            Ws[nb2][(ac + 3) * 68 + ar0] = rw.w;
            __syncthreads();
            buf = nb2;
        }
    }
    float bvx, bvy, bvz, bvw;
    if (gate_perm) {
        int n0 = bn + tx * 4;
        bvx = bias[((n0 + 0) & 3) * 256 + ((n0 + 0) >> 2)];
        bvy = bias[((n0 + 1) & 3) * 256 + ((n0 + 1) >> 2)];
        bvz = bias[((n0 + 2) & 3) * 256 + ((n0 + 2) >> 2)];
        bvw = bias[((n0 + 3) & 3) * 256 + ((n0 + 3) >> 2)];
    } else {
        float4 bv = *(const float4*)&bias[bn + tx * 4];
        bvx = bv.x; bvy = bv.y; bvz = bv.z; bvw = bv.w;
    }
#pragma unroll
    for (int i = 0; i < 8; i++) {
        int m = bm + ty * 8 + i;
        float4 o;
        o.x = acc[i][0] + bvx; o.y = acc[i][1] + bvy;
        o.z = acc[i][2] + bvz; o.w = acc[i][3] + bvw;
        if (relu) {
            o.x = fmaxf(o.x, 0.f); o.y = fmaxf(o.y, 0.f);
            o.z = fmaxf(o.z, 0.f); o.w = fmaxf(o.w, 0.f);
        }
        *(float4*)&C[(size_t)m * N + bn + tx * 4] = o;
    }
}

// ---------------- persistent encoder scan: 2 batches/thread, 4-way k-split -
// 512 threads; warp map: kh = wrp>>2 (k quarter), u = wrp&3; lane = b0 (0..31),
// each thread handles batches b0 and b0+32. Per 4-k: 6 LDS.128 / 16 FFMA2.
// out stores buffered in smem, flushed every 8 steps (release-drain smoothing).
// xw is gate-interleaved: xw[(b*Tl+t)*1024 + hu*4 + gate]
#define ENC_SMEM ((16 * 264 + 64 * 260 + 3 * 256 * 4 + 8 * 256) * 4)
__global__ __launch_bounds__(512) void enc_scan(
    const float* __restrict__ xw_f, const float* __restrict__ xw_b,
    const float* __restrict__ whh_f, const float* __restrict__ whh_b,
    float* __restrict__ out, int Tl, unsigned epoch0)
{
    extern __shared__ float smem[];
    float* sh_w = smem;                     // 16 x 256 (pitch 264)
    float* sh_x = smem + 16 * 264;          // 64 x 256 (pitch 260)
    float* sh_p = sh_x + 64 * 260;          // [kh-1][u*64+b][4] = 3*256*4
    float* sh_o = sh_p + 3 * 256 * 4;       // 8 steps x 256 (b*4+u)

    int tid = threadIdx.x;
    int lane = tid & 31, wrp = tid >> 5;
    int kh = wrp >> 2;                      // 0..3
    int u = wrp & 3;
    int b0 = lane;                          // batches b0 and b0+32
    int dir = blockIdx.y;
    int hu0 = blockIdx.x << 2;
    int hu = hu0 + u;
    unsigned epoch = epoch0;
    const unsigned nb = gridDim.x;
    unsigned* ctr = &g_barE[dir];

    const float* xw  = dir ? xw_b  : xw_f;
    const float* Whh = dir ? whh_b : whh_f;

    for (int i = tid; i < 16 * 64; i += 512) {
        int r = i >> 6, kq = (i & 63) << 2;
        int grow = ((r >> 2) << 8) + hu0 + (r & 3);
        *(float4*)&sh_w[r * 264 + kq] = *(const float4*)&Whh[(size_t)grow * 256 + kq];
    }

    float cA = 0.f, cB = 0.f;
    if (kh == 0) {
        __stcg(&g_h[(size_t)(0 * 2 + dir) * 64 * 256 + b0 * 256 + hu], 0.f);
        __stcg(&g_h[(size_t)(0 * 2 + dir) * 64 * 256 + (b0 + 32) * 256 + hu], 0.f);
    }
    gbar(ctr, epoch, nb);

    const float* wr0 = &sh_w[(0 * 4 + u) * 264 + kh * 64];
    const float* wr1 = &sh_w[(1 * 4 + u) * 264 + kh * 64];
    const float* wr2 = &sh_w[(2 * 4 + u) * 264 + kh * 64];
    const float* wr3 = &sh_w[(3 * 4 + u) * 264 + kh * 64];
    const float* hpA = &sh_x[b0 * 260 + kh * 64];
    const float* hpB = &sh_x[(b0 + 32) * 260 + kh * 64];

    float4 xgA = make_float4(0.f, 0.f, 0.f, 0.f);
    float4 xgB = make_float4(0.f, 0.f, 0.f, 0.f);
    if (kh == 0) {
        int tt0 = dir ? (Tl - 1) : 0;
        xgA = __ldg((const float4*)&xw[((size_t)b0 * Tl + tt0) * 1024 + (hu << 2)]);
        xgB = __ldg((const float4*)&xw[((size_t)(b0 + 32) * Tl + tt0) * 1024 + (hu << 2)]);
    }

    for (int t = 0; t < Tl; t++) {
        int pin = t & 1, pout = pin ^ 1;
        const float* hin = g_h + (size_t)(pin * 2 + dir) * 64 * 256;

        // fill 64x256 h (8 float4 per thread)
        for (int i = tid; i < 4096; i += 512) {
            int bb = i >> 6, kq = (i & 63) << 2;
            *(float4*)&sh_x[bb * 260 + kq] = __ldcg((const float4*)&hin[bb * 256 + kq]);
        }
        __syncthreads();

        ull A0 = 0ull, A1 = 0ull, A2 = 0ull, A3 = 0ull;
        ull B0 = 0ull, B1 = 0ull, B2 = 0ull, B3 = 0ull;
#pragma unroll 8
        for (int kk = 0; kk < 64; kk += 4) {
            UP hA, hB, w0, w1, w2, w3;
            hA.f = *(const float4*)&hpA[kk];
            hB.f = *(const float4*)&hpB[kk];
            w0.f = *(const float4*)&wr0[kk];
            w1.f = *(const float4*)&wr1[kk];
            w2.f = *(const float4*)&wr2[kk];
            w3.f = *(const float4*)&wr3[kk];
            fma2(A0, hA.u[0], w0.u[0]); fma2(A1, hA.u[0], w1.u[0]);
            fma2(A2, hA.u[0], w2.u[0]); fma2(A3, hA.u[0], w3.u[0]);
            fma2(B0, hB.u[0], w0.u[0]); fma2(B1, hB.u[0], w1.u[0]);
            fma2(B2, hB.u[0], w2.u[0]); fma2(B3, hB.u[0], w3.u[0]);
            fma2(A0, hA.u[1], w0.u[1]); fma2(A1, hA.u[1], w1.u[1]);
            fma2(A2, hA.u[1], w2.u[1]); fma2(A3, hA.u[1], w3.u[1]);
            fma2(B0, hB.u[1], w0.u[1]); fma2(B1, hB.u[1], w1.u[1]);
            fma2(B2, hB.u[1], w2.u[1]); fma2(B3, hB.u[1], w3.u[1]);
        }
        U2 a0, a1, a2, a3, e0, e1, e2, e3;
        a0.u = A0; a1.u = A1; a2.u = A2; a3.u = A3;
        e0.u = B0; e1.u = B1; e2.u = B2; e3.u = B3;
        if (kh > 0) {
            float* pA = &sh_p[((kh - 1) * 256 + u * 64 + b0) * 4];
            float* pB = &sh_p[((kh - 1) * 256 + u * 64 + b0 + 32) * 4];
            *(float4*)pA = make_float4(a0.f.x + a0.f.y, a1.f.x + a1.f.y,
                                       a2.f.x + a2.f.y, a3.f.x + a3.f.y);
            *(float4*)pB = make_float4(e0.f.x + e0.f.y, e1.f.x + e1.f.y,
                                       e2.f.x + e2.f.y, e3.f.x + e3.f.y);
        }
        __syncthreads();

        if (kh == 0) {
            float4 zA = make_float4(a0.f.x + a0.f.y + xgA.x, a1.f.x + a1.f.y + xgA.y,
                                    a2.f.x + a2.f.y + xgA.z, a3.f.x + a3.f.y + xgA.w);
            float4 zB = make_float4(e0.f.x + e0.f.y + xgB.x, e1.f.x + e1.f.y + xgB.y,
                                    e2.f.x + e2.f.y + xgB.z, e3.f.x + e3.f.y + xgB.w);
#pragma unroll
            for (int q = 1; q < 4; q++) {
                float4 pA = *(const float4*)&sh_p[((q - 1) * 256 + u * 64 + b0) * 4];
                float4 pB = *(const float4*)&sh_p[((q - 1) * 256 + u * 64 + b0 + 32) * 4];
                zA.x += pA.x; zA.y += pA.y; zA.z += pA.z; zA.w += pA.w;
                zB.x += pB.x; zB.y += pB.y; zB.z += pB.z; zB.w += pB.w;
            }
            float siA = 1.f / (1.f + expf(-zA.x));
            float sfA = 1.f / (1.f + expf(-zA.y));
            float soA = 1.f / (1.f + expf(-zA.w));
            float cnA = sfA * cA + siA * tanhf(zA.z);
            float hnA = soA * tanhf(cnA);
            cA = cnA;
            float siB = 1.f / (1.f + expf(-zB.x));
            float sfB = 1.f / (1.f + expf(-zB.y));
            float soB = 1.f / (1.f + expf(-zB.w));
            float cnB = sfB * cB + siB * tanhf(zB.z);
            float hnB = soB * tanhf(cnB);
            cB = cnB;
            float* hop = g_h + (size_t)(pout * 2 + dir) * 64 * 256;
            __stcg(&hop[b0 * 256 + hu], hnA);
            __stcg(&hop[(b0 + 32) * 256 + hu], hnB);
            sh_o[(t & 7) * 256 + (b0 << 2) + u] = hnA;
            sh_o[(t & 7) * 256 + ((b0 + 32) << 2) + u] = hnB;
        }

        gbar_arrive(ctr);
        if (kh == 0) {
            if ((t & 7) == 7) {            // flush 8 buffered out-steps
                int tbase = t & ~7;
#pragma unroll
                for (int j = 0; j < 8; j++) {
                    int ta = tbase + j;
                    int tta = dir ? (Tl - 1 - ta) : ta;
                    out[((size_t)b0 * Tl + tta) * 512 + dir * 256 + hu] =
                        sh_o[j * 256 + (b0 << 2) + u];
                    out[((size_t)(b0 + 32) * Tl + tta) * 512 + dir * 256 + hu] =
                        sh_o[j * 256 + ((b0 + 32) << 2) + u];
                }
            }
            if (t + 1 < Tl) {
                int tn = dir ? (Tl - 2 - t) : (t + 1);
                xgA = __ldg((const float4*)&xw[((size_t)b0 * Tl + tn) * 1024 + (hu << 2)]);
                xgB = __ldg((const float4*)&xw[((size_t)(b0 + 32) * Tl + tn) * 1024 + (hu << 2)]);
            }
        }
        gbar_wait(ctr, epoch, nb);
    }
    if (kh == 0) {
        g_c[(size_t)(dir * 64 + b0) * 256 + hu] = cA;
        g_c[(size_t)(dir * 64 + b0 + 32) * 256 + hu] = cB;
    }
}

// ---------------- persistent decoder (R14-proven) ----------------
#define DEC_SMEM ((16 * 1032 + 64 * 516 + 512 + 128 + 256 + 512 + 64 + 256) * 4)
__global__ __launch_bounds__(256) void dec_scan(
    const float* __restrict__ sWih, const float* __restrict__ sWhh,
    const float* __restrict__ sb, const int* __restrict__ gt,
    const float* __restrict__ phi_b,
    const float* __restrict__ fcW, const float* __restrict__ fcb,
    float* __restrict__ out_lps)
{
    extern __shared__ float smem[];
    float* sh_w  = smem;
    float* sh_x  = sh_w + 16 * 1032;
    float* sh_h  = sh_x + 64 * 516;
    float* sh_q  = sh_h + 512;
    float* sh_e  = sh_q + 128;
    float* sh_c2 = sh_e + 256;
    float* sh_l  = sh_c2 + 512;
    float* sr    = sh_l + 64;

    int tid = threadIdx.x;
    int lane = tid & 31, wrp = tid >> 5;
    int u = wrp & 3, bh = wrp >> 2;
    int b = bh * 32 + lane;
    int hu0 = blockIdx.x << 2;
    int hu = hu0 + u;
    unsigned epoch = 0;
    const unsigned nb = gridDim.x;
    unsigned* ctr = &g_barD;

    for (int i = tid; i < 16 * 256; i += 256) {
        int r = i >> 8, kq = (i & 255) << 2;
        int grow = (r >> 2) * SHID + hu0 + (r & 3);
        float4 v;
        if (kq < 512) v = *(const float4*)&sWih[(size_t)grow * 560 + 48 + kq];
        else          v = *(const float4*)&sWhh[(size_t)grow * 512 + (kq - 512)];
        *(float4*)&sh_w[r * 1032 + kq] = v;
    }

    float creg = 0.f;
    __stcg(&g_dh[(size_t)b * 512 + hu], 0.f);
    __stcg(&g_ctx[(size_t)b * 512 + hu], __ldg(&g_feats[(size_t)b * 256 * 512 + hu]));
    gbar(ctr, epoch, nb);

    float bi0 = sb[0 * SHID + hu], bi1 = sb[1 * SHID + hu];
    float bi2 = sb[2 * SHID + hu], bi3 = sb[3 * SHID + hu];

    for (int t = 0; t < TDEC; t++) {
        int pin = t & 1, pout = pin ^ 1;
        int tok = (t == 0) ? 0 : gt[b * TDEC + (t - 1)];
        U2 A0, A1, A2, A3;
        A0.f = make_float2(sWih[(size_t)(0 * SHID + hu) * 560 + tok] + bi0, 0.f);
        A1.f = make_float2(sWih[(size_t)(1 * SHID + hu) * 560 + tok] + bi1, 0.f);
        A2.f = make_float2(sWih[(size_t)(2 * SHID + hu) * 560 + tok] + bi2, 0.f);
        A3.f = make_float2(sWih[(size_t)(3 * SHID + hu) * 560 + tok] + bi3, 0.f);

        const float* hin = g_dh + (size_t)pin * 64 * 512;
#pragma unroll
        for (int c = 0; c < 2; c++) {
            __syncthreads();
            const float* src = (c == 0) ? g_ctx : hin;
            for (int i = tid; i < 64 * 128; i += 256) {
                int bb = i >> 7, kq = (i & 127) << 2;
                *(float4*)&sh_x[bb * 516 + kq] = __ldcg((const float4*)&src[(size_t)bb * 512 + kq]);
            }
            __syncthreads();
            const float* w0p = &sh_w[(0 * 4 + u) * 1032 + c * 512];
            const float* w1p = &sh_w[(1 * 4 + u) * 1032 + c * 512];
            const float* w2p = &sh_w[(2 * 4 + u) * 1032 + c * 512];
            const float* w3p = &sh_w[(3 * 4 + u) * 1032 + c * 512];
            const float* hp  = &sh_x[b * 516];
#pragma unroll 8
            for (int kk = 0; kk < 512; kk += 4) {
                UP h, w0, w1, w2, w3;
                h.f  = *(const float4*)&hp[kk];
                w0.f = *(const float4*)&w0p[kk];
                w1.f = *(const float4*)&w1p[kk];
                w2.f = *(const float4*)&w2p[kk];
                w3.f = *(const float4*)&w3p[kk];
                fma2(A0.u, h.u[0], w0.u[0]); fma2(A1.u, h.u[0], w1.u[0]);
                fma2(A2.u, h.u[0], w2.u[0]); fma2(A3.u, h.u[0], w3.u[0]);
                fma2(A0.u, h.u[1], w0.u[1]); fma2(A1.u, h.u[1], w1.u[1]);
                fma2(A2.u, h.u[1], w2.u[1]); fma2(A3.u, h.u[1], w3.u[1]);
            }
        }
        float acc0 = A0.f.x + A0.f.y;
        float acc1 = A1.f.x + A1.f.y;
        float acc2 = A2.f.x + A2.f.y;
        float acc3 = A3.f.x + A3.f.y;
        float si = 1.f / (1.f + expf(-acc0));
        float sf = 1.f / (1.f + expf(-acc1));
        float so = 1.f / (1.f + expf(-acc3));
        float cn = sf * creg + si * tanhf(acc2);
        float hn = so * tanhf(cn);
        creg = cn;
        __stcg(&g_dh[(size_t)pout * 64 * 512 + b * 512 + hu], hn);
        gbar(ctr, epoch, nb);

        if (blockIdx.x < 64) {
            int bb = blockIdx.x;
            const float* h = g_dh + (size_t)pout * 64 * 512 + (size_t)bb * 512;
            for (int i = tid; i < 512; i += 256) sh_h[i] = __ldcg(&h[i]);
            __syncthreads();

            {
                int j = tid >> 1, hf = tid & 1;
                const float* pw = g_phiWt + (size_t)hf * 256 * 128;
                const float* hh = sh_h + hf * 256;
                float a0 = 0.f, a1 = 0.f, a2 = 0.f, a3 = 0.f;
                for (int k = 0; k < 256; k += 4) {
                    a0 += hh[k + 0] * pw[(k + 0) * 128 + j];
                    a1 += hh[k + 1] * pw[(k + 1) * 128 + j];
                    a2 += hh[k + 2] * pw[(k + 2) * 128 + j];
                    a3 += hh[k + 3] * pw[(k + 3) * 128 + j];
                }
                sr[tid] = a0 + a1 + a2 + a3;
            }
            __syncthreads();
            if (tid < 128) {
                float q = sr[2 * tid] + sr[2 * tid + 1] + phi_b[tid];
                sh_q[tid] = q > 0.f ? q : 0.f;
            }
            __syncthreads();

            {
                const float* cfp = g_cf + ((size_t)bb * 256 + tid) * 128;
                float a0 = 0.f, a1 = 0.f, a2 = 0.f, a3 = 0.f;
                for (int j = 0; j < 128; j += 4) {
                    a0 += sh_q[j + 0] * cfp[j + 0];
                    a1 += sh_q[j + 1] * cfp[j + 1];
                    a2 += sh_q[j + 2] * cfp[j + 2];
                    a3 += sh_q[j + 3] * cfp[j + 3];
                }
                sh_e[tid] = a0 + a1 + a2 + a3;
            }
            __syncthreads();

            float v = sh_e[tid];
            sr[tid] = v; __syncthreads();
            for (int s = 128; s > 0; s >>= 1) { if (tid < s) sr[tid] = fmaxf(sr[tid], sr[tid + s]); __syncthreads(); }
            float m = sr[0]; __syncthreads();
            float e = expf(v - m);
            sr[tid] = e; __syncthreads();
            for (int s = 128; s > 0; s >>= 1) { if (tid < s) sr[tid] += sr[tid + s]; __syncthreads(); }
            float inv = 1.f / sr[0];
            __syncthreads();
            sh_e[tid] = e * inv;
            __syncthreads();

            for (int d0 = 0; d0 < 512; d0 += 256) {
                int d = d0 + tid;
                const float* fp = g_feats + (size_t)bb * 256 * 512 + d;
                float a0 = 0.f, a1 = 0.f, a2 = 0.f, a3 = 0.f;
                for (int tt2 = 0; tt2 < 256; tt2 += 4) {
                    a0 += sh_e[tt2 + 0] * fp[(size_t)(tt2 + 0) * 512];
                    a1 += sh_e[tt2 + 1] * fp[(size_t)(tt2 + 1) * 512];
                    a2 += sh_e[tt2 + 2] * fp[(size_t)(tt2 + 2) * 512];
                    a3 += sh_e[tt2 + 3] * fp[(size_t)(tt2 + 3) * 512];
                }
                float cv = a0 + a1 + a2 + a3;
                sh_c2[d] = cv;
                __stcg(&g_ctx[(size_t)bb * 512 + d], cv);
            }
            __syncthreads();

            if (tid < 192) {
                int v2 = tid >> 2, part = tid & 3;
                const float* wr = fcW + (size_t)v2 * 1024 + part * 256;
                const float* src = (part < 2) ? (sh_h + part * 256) : (sh_c2 + (part - 2) * 256);
                float a0 = 0.f, a1 = 0.f, a2 = 0.f, a3 = 0.f;
                for (int k = 0; k < 256; k += 4) {
                    a0 += src[k + 0] * wr[k + 0];
                    a1 += src[k + 1] * wr[k + 1];
                    a2 += src[k + 2] * wr[k + 2];
                    a3 += src[k + 3] * wr[k + 3];
                }
                sr[tid] = a0 + a1 + a2 + a3;
            }
            __syncthreads();
            if (tid < 48) {
                sh_l[tid] = sr[tid * 4] + sr[tid * 4 + 1] + sr[tid * 4 + 2] + sr[tid * 4 + 3] + fcb[tid];
            }
            __syncthreads();
            if (tid < 48) {
                float m2 = -1e30f;
                for (int j = 0; j < 48; j++) m2 = fmaxf(m2, sh_l[j]);
                float s2 = 0.f;
                for (int j = 0; j < 48; j++) s2 += expf(sh_l[j] - m2);
                out_lps[(size_t)bb * TDEC * NVOC + (size_t)t * NVOC + tid] = sh_l[tid] - m2 - logf(s2);
            }
        }
        gbar(ctr, epoch, nb);
    }
}

// ---------------- small helpers ----------------
__global__ void transpose_phi(const float* __restrict__ W) {
    int j = blockIdx.x;
    for (int k = threadIdx.x; k < 512; k += 256) g_phiWt[k * 128 + j] = W[j * 512 + k];
}

__global__ void fin_hc(float* __restrict__ out) {
    int b = blockIdx.x;
    for (int i = threadIdx.x; i < 1024; i += 256) {
        int q = i >> 8, r = i & 255;
        float v;
        if (q == 0)      v = g_h[(size_t)(0 * 2 + 0) * 64 * 256 + b * 256 + r];
        else if (q == 1) v = g_h[(size_t)(0 * 2 + 1) * 64 * 256 + b * 256 + r];
        else if (q == 2) v = g_c[(size_t)(0 * 64 + b) * 256 + r];
        else             v = g_c[(size_t)(1 * 64 + b) * 256 + r];
        out[(size_t)b * 1024 + i] = v;
    }
}

// ---------------- host launcher ----------------
extern "C" void kernel_launch(void* const* d_in, const int* in_sizes, int n_in,
                              void* d_out, int out_size)
{
    const float* inputs = (const float*)d_in[0];
    const int*   gt     = (const int*)d_in[1];
    const float* W[27];
    for (int i = 0; i < 27; i++) W[i] = (const float*)d_in[i + 2];

    float *xw0, *xw1, *out0, *out1, *feats, *cf;
    cudaGetSymbolAddress((void**)&xw0, g_xw0);
    cudaGetSymbolAddress((void**)&xw1, g_xw1);
    cudaGetSymbolAddress((void**)&out0, g_out0);
    cudaGetSymbolAddress((void**)&out1, g_out1);
    cudaGetSymbolAddress((void**)&feats, g_feats);
    cudaGetSymbolAddress((void**)&cf, g_cf);

    cudaFuncSetAttribute(enc_scan, cudaFuncAttributeMaxDynamicSharedMemorySize, ENC_SMEM);
    cudaFuncSetAttribute(dec_scan, cudaFuncAttributeMaxDynamicSharedMemorySize, DEC_SMEM);

    float* dout = (float*)d_out;

    const float* A = inputs;
    float* outs[3] = {out0, out1, feats};
    int Tl = 1024, K = 160;
    unsigned ebase = 0;
    for (int l = 0; l < 3; l++) {
        int M = 64 * Tl;
        dim3 gg(1024 / 64, M / 128);
        gemm_bias<<<gg, 256>>>(A, W[l * 6 + 0], W[l * 6 + 2], xw0, M, 1024, K, 0, 1);
        gemm_bias<<<gg, 256>>>(A, W[l * 6 + 3], W[l * 6 + 5], xw1, M, 1024, K, 0, 1);
        if (l == 0) reset_bars<<<1, 32>>>();
        enc_scan<<<dim3(64, 2), 512, ENC_SMEM>>>(xw0, xw1, W[l * 6 + 1], W[l * 6 + 4],
                                                 outs[l], Tl, ebase);
        ebase += 64u * (unsigned)(Tl + 1);
        A = outs[l];
        Tl >>= 1;
        K = 1024;
    }

    // comp_feat = relu(feats @ psi_W^T + psi_b)   [16384,128]
    gemm_bias<<<dim3(2, 16384 / 128), 256>>>(feats, W[23], W[24], cf, 16384, 128, 512, 1, 0);
    transpose_phi<<<128, 256>>>(W[21]);
    fin_hc<<<64, 256>>>(dout + (size_t)BATCH * TDEC * NVOC);

    // ---------------- decoder ----------------
    dec_scan<<<128, 256, DEC_SMEM>>>(W[18], W[19], W[20], gt, W[22], W[25], W[26], dout);
}

// round 17
// speedup vs baseline: 1.0929x; 1.0297x over previous
#include <cuda_runtime.h>
#include <math.h>

// ---------------- problem constants ----------------
#define BATCH 64
#define TDEC  150
#define NVOC  48
#define LHID  256
#define SHID  512
#define NMLP  128

typedef unsigned long long ull;

// ---------------- device scratch ----------------
__device__ float g_xw0[64*1024*1024];
__device__ float g_xw1[64*1024*1024];
__device__ float g_out0[64*1024*512];
__device__ float g_out1[64*512*512];
__device__ float g_feats[64*256*512];
__device__ float g_cf[64*256*128];
__device__ float g_h[2*2*64*256];          // [parity][dir][b][256]
__device__ float g_c[2*64*256];
__device__ float g_dh[2*64*512];
__device__ float g_ctx[64*512];
__device__ float g_phiWt[512*128];
__device__ unsigned g_barE[2];             // per-direction encoder barriers
__device__ unsigned g_barD;                // decoder barrier

// ---------------- split-phase grid barrier (proven primitives) ----------
__device__ __forceinline__ void gbar_arrive(unsigned* ctr)
{
    __syncthreads();
    if (threadIdx.x == 0) {
        asm volatile("red.release.gpu.global.add.u32 [%0], %1;"
                     :: "l"(ctr), "r"(1u) : "memory");
    }
}
__device__ __forceinline__ void gbar_wait(unsigned* ctr, unsigned& epoch, unsigned nb)
{
    if (threadIdx.x == 0) {
        unsigned target = epoch + nb;
        unsigned v;
        int spins = 0;
        for (;;) {
            asm volatile("ld.acquire.gpu.global.u32 %0, [%1];"
                         : "=r"(v) : "l"(ctr) : "memory");
            if (v >= target) break;
            if (++spins > 16) __nanosleep(64);
        }
    }
    epoch += nb;
    __syncthreads();
}
__device__ __forceinline__ void gbar(unsigned* ctr, unsigned& epoch, unsigned nb)
{
    gbar_arrive(ctr);
    gbar_wait(ctr, epoch, nb);
}

// ---------------- packed fp32x2 FMA (SASS FFMA2) ----------------
__device__ __forceinline__ void fma2(ull& d, ull a, ull b)
{
    asm("fma.rn.f32x2 %0, %1, %2, %0;" : "+l"(d) : "l"(a), "l"(b));
}

union UP { float4 f; ull u[2]; };
union U2 { ull u; float2 f; };

// ---------------- barrier reset ----------------
__global__ void reset_bars() {
    if (threadIdx.x == 0 && blockIdx.x == 0) {
        g_barE[0] = 0; g_barE[1] = 0; g_barD = 0;
    }
}

// ---------------- fp32 GEMM, software-pipelined (R14-proven) ---------------
__global__ __launch_bounds__(256) void gemm_bias(
    const float* __restrict__ A, const float* __restrict__ W,
    const float* __restrict__ bias, float* __restrict__ C,
    int M, int N, int K, int relu, int gate_perm)
{
    __shared__ float As[2][16 * 132];
    __shared__ float Ws[2][16 * 68];
    int bm = blockIdx.y << 7, bn = blockIdx.x << 6;
    int tid = threadIdx.x;
    int ty = tid >> 4, tx = tid & 15;
    const float* Ap = A + (size_t)bm * K;

    int ar0 = tid >> 2, ac = (tid & 3) << 2;
    int ar1 = ar0 + 64;
    int nprime = bn + ar0;
    int nrow = gate_perm ? ((nprime & 3) * 256 + (nprime >> 2)) : nprime;
    const float* ApRow0 = Ap + (size_t)ar0 * K;
    const float* ApRow1 = Ap + (size_t)ar1 * K;
    const float* WpRow  = W + (size_t)nrow * K;

    float acc[8][4];
#pragma unroll
    for (int i = 0; i < 8; i++)
#pragma unroll
        for (int j = 0; j < 4; j++) acc[i][j] = 0.f;

    float4 ra0 = *(const float4*)&ApRow0[ac];
    float4 ra1 = *(const float4*)&ApRow1[ac];
    float4 rw  = *(const float4*)&WpRow[ac];
    {
        As[0][(ac + 0) * 132 + ar0] = ra0.x;
        As[0][(ac + 1) * 132 + ar0] = ra0.y;
        As[0][(ac + 2) * 132 + ar0] = ra0.z;
        As[0][(ac + 3) * 132 + ar0] = ra0.w;
        As[0][(ac + 0) * 132 + ar1] = ra1.x;
        As[0][(ac + 1) * 132 + ar1] = ra1.y;
        As[0][(ac + 2) * 132 + ar1] = ra1.z;
        As[0][(ac + 3) * 132 + ar1] = ra1.w;
        Ws[0][(ac + 0) * 68 + ar0] = rw.x;
        Ws[0][(ac + 1) * 68 + ar0] = rw.y;
        Ws[0][(ac + 2) * 68 + ar0] = rw.z;
        Ws[0][(ac + 3) * 68 + ar0] = rw.w;
    }
    __syncthreads();

    int buf = 0;
    for (int k0 = 0; k0 < K; k0 += 16) {
        int more = (k0 + 16 < K);
        if (more) {
            ra0 = *(const float4*)&ApRow0[k0 + 16 + ac];
            ra1 = *(const float4*)&ApRow1[k0 + 16 + ac];
            rw  = *(const float4*)&WpRow[k0 + 16 + ac];
        }
        const float* Ab = As[buf];
        const float* Wb = Ws[buf];
#pragma unroll
        for (int kk = 0; kk < 16; kk++) {
            float4 a0 = *(const float4*)&Ab[kk * 132 + ty * 8];
            float4 a1 = *(const float4*)&Ab[kk * 132 + ty * 8 + 4];
            float4 w  = *(const float4*)&Wb[kk * 68 + tx * 4];
            acc[0][0] += a0.x * w.x; acc[0][1] += a0.x * w.y; acc[0][2] += a0.x * w.z; acc[0][3] += a0.x * w.w;
            acc[1][0] += a0.y * w.x; acc[1][1] += a0.y * w.y; acc[1][2] += a0.y * w.z; acc[1][3] += a0.y * w.w;
            acc[2][0] += a0.z * w.x; acc[2][1] += a0.z * w.y; acc[2][2] += a0.z * w.z; acc[2][3] += a0.z * w.w;
            acc[3][0] += a0.w * w.x; acc[3][1] += a0.w * w.y; acc[3][2] += a0.w * w.z; acc[3][3] += a0.w * w.w;
            acc[4][0] += a1.x * w.x; acc[4][1] += a1.x * w.y; acc[4][2] += a1.x * w.z; acc[4][3] += a1.x * w.w;
            acc[5][0] += a1.y * w.x; acc[5][1] += a1.y * w.y; acc[5][2] += a1.y * w.z; acc[5][3] += a1.y * w.w;
            acc[6][0] += a1.z * w.x; acc[6][1] += a1.z * w.y; acc[6][2] += a1.z * w.z; acc[6][3] += a1.z * w.w;
            acc[7][0] += a1.w * w.x; acc[7][1] += a1.w * w.y; acc[7][2] += a1.w * w.z; acc[7][3] += a1.w * w.w;
        }
        if (more) {
            int nb2 = buf ^ 1;
            As[nb2][(ac + 0) * 132 + ar0] = ra0.x;
            As[nb2][(ac + 1) * 132 + ar0] = ra0.y;
            As[nb2][(ac + 2) * 132 + ar0] = ra0.z;
            As[nb2][(ac + 3) * 132 + ar0] = ra0.w;
            As[nb2][(ac + 0) * 132 + ar1] = ra1.x;
            As[nb2][(ac + 1) * 132 + ar1] = ra1.y;
            As[nb2][(ac + 2) * 132 + ar1] = ra1.z;
            As[nb2][(ac + 3) * 132 + ar1] = ra1.w;
            Ws[nb2][(ac + 0) * 68 + ar0] = rw.x;
            Ws[nb2][(ac + 1) * 68 + ar0] = rw.y;
            Ws[nb2][(ac + 2) * 68 + ar0] = rw.z;
            Ws[nb2][(ac + 3) * 68 + ar0] = rw.w;
            __syncthreads();
            buf = nb2;
        }
    }
    float bvx, bvy, bvz, bvw;
    if (gate_perm) {
        int n0 = bn + tx * 4;
        bvx = bias[((n0 + 0) & 3) * 256 + ((n0 + 0) >> 2)];
        bvy = bias[((n0 + 1) & 3) * 256 + ((n0 + 1) >> 2)];
        bvz = bias[((n0 + 2) & 3) * 256 + ((n0 + 2) >> 2)];
        bvw = bias[((n0 + 3) & 3) * 256 + ((n0 + 3) >> 2)];
    } else {
        float4 bv = *(const float4*)&bias[bn + tx * 4];
        bvx = bv.x; bvy = bv.y; bvz = bv.z; bvw = bv.w;
    }
#pragma unroll
    for (int i = 0; i < 8; i++) {
        int m = bm + ty * 8 + i;
        float4 o;
        o.x = acc[i][0] + bvx; o.y = acc[i][1] + bvy;
        o.z = acc[i][2] + bvz; o.w = acc[i][3] + bvw;
        if (relu) {
            o.x = fmaxf(o.x, 0.f); o.y = fmaxf(o.y, 0.f);
            o.z = fmaxf(o.z, 0.f); o.w = fmaxf(o.w, 0.f);
        }
        *(float4*)&C[(size_t)m * N + bn + tx * 4] = o;
    }
}

// ---------------- persistent encoder scan (R16-proven champion) ------------
#define ENC_SMEM ((16 * 264 + 64 * 260 + 3 * 256 * 4 + 8 * 256) * 4)
__global__ __launch_bounds__(512) void enc_scan(
    const float* __restrict__ xw_f, const float* __restrict__ xw_b,
    const float* __restrict__ whh_f, const float* __restrict__ whh_b,
    float* __restrict__ out, int Tl, unsigned epoch0)
{
    extern __shared__ float smem[];
    float* sh_w = smem;                     // 16 x 256 (pitch 264)
    float* sh_x = smem + 16 * 264;          // 64 x 256 (pitch 260)
    float* sh_p = sh_x + 64 * 260;          // [kh-1][u*64+b][4]
    float* sh_o = sh_p + 3 * 256 * 4;       // 8 steps x 256

    int tid = threadIdx.x;
    int lane = tid & 31, wrp = tid >> 5;
    int kh = wrp >> 2;
    int u = wrp & 3;
    int b0 = lane;
    int dir = blockIdx.y;
    int hu0 = blockIdx.x << 2;
    int hu = hu0 + u;
    unsigned epoch = epoch0;
    const unsigned nb = gridDim.x;
    unsigned* ctr = &g_barE[dir];

    const float* xw  = dir ? xw_b  : xw_f;
    const float* Whh = dir ? whh_b : whh_f;

    for (int i = tid; i < 16 * 64; i += 512) {
        int r = i >> 6, kq = (i & 63) << 2;
        int grow = ((r >> 2) << 8) + hu0 + (r & 3);
        *(float4*)&sh_w[r * 264 + kq] = *(const float4*)&Whh[(size_t)grow * 256 + kq];
    }

    float cA = 0.f, cB = 0.f;
    if (kh == 0) {
        __stcg(&g_h[(size_t)(0 * 2 + dir) * 64 * 256 + b0 * 256 + hu], 0.f);
        __stcg(&g_h[(size_t)(0 * 2 + dir) * 64 * 256 + (b0 + 32) * 256 + hu], 0.f);
    }
    gbar(ctr, epoch, nb);

    const float* wr0 = &sh_w[(0 * 4 + u) * 264 + kh * 64];
    const float* wr1 = &sh_w[(1 * 4 + u) * 264 + kh * 64];
    const float* wr2 = &sh_w[(2 * 4 + u) * 264 + kh * 64];
    const float* wr3 = &sh_w[(3 * 4 + u) * 264 + kh * 64];
    const float* hpA = &sh_x[b0 * 260 + kh * 64];
    const float* hpB = &sh_x[(b0 + 32) * 260 + kh * 64];

    float4 xgA = make_float4(0.f, 0.f, 0.f, 0.f);
    float4 xgB = make_float4(0.f, 0.f, 0.f, 0.f);
    if (kh == 0) {
        int tt0 = dir ? (Tl - 1) : 0;
        xgA = __ldg((const float4*)&xw[((size_t)b0 * Tl + tt0) * 1024 + (hu << 2)]);
        xgB = __ldg((const float4*)&xw[((size_t)(b0 + 32) * Tl + tt0) * 1024 + (hu << 2)]);
    }

    for (int t = 0; t < Tl; t++) {
        int pin = t & 1, pout = pin ^ 1;
        const float* hin = g_h + (size_t)(pin * 2 + dir) * 64 * 256;

        for (int i = tid; i < 4096; i += 512) {
            int bb = i >> 6, kq = (i & 63) << 2;
            *(float4*)&sh_x[bb * 260 + kq] = __ldcg((const float4*)&hin[bb * 256 + kq]);
        }
        __syncthreads();

        ull A0 = 0ull, A1 = 0ull, A2 = 0ull, A3 = 0ull;
        ull B0 = 0ull, B1 = 0ull, B2 = 0ull, B3 = 0ull;
#pragma unroll 8
        for (int kk = 0; kk < 64; kk += 4) {
            UP hA, hB, w0, w1, w2, w3;
            hA.f = *(const float4*)&hpA[kk];
            hB.f = *(const float4*)&hpB[kk];
            w0.f = *(const float4*)&wr0[kk];
            w1.f = *(const float4*)&wr1[kk];
            w2.f = *(const float4*)&wr2[kk];
            w3.f = *(const float4*)&wr3[kk];
            fma2(A0, hA.u[0], w0.u[0]); fma2(A1, hA.u[0], w1.u[0]);
            fma2(A2, hA.u[0], w2.u[0]); fma2(A3, hA.u[0], w3.u[0]);
            fma2(B0, hB.u[0], w0.u[0]); fma2(B1, hB.u[0], w1.u[0]);
            fma2(B2, hB.u[0], w2.u[0]); fma2(B3, hB.u[0], w3.u[0]);
            fma2(A0, hA.u[1], w0.u[1]); fma2(A1, hA.u[1], w1.u[1]);
            fma2(A2, hA.u[1], w2.u[1]); fma2(A3, hA.u[1], w3.u[1]);
            fma2(B0, hB.u[1], w0.u[1]); fma2(B1, hB.u[1], w1.u[1]);
            fma2(B2, hB.u[1], w2.u[1]); fma2(B3, hB.u[1], w3.u[1]);
        }
        U2 a0, a1, a2, a3, e0, e1, e2, e3;
        a0.u = A0; a1.u = A1; a2.u = A2; a3.u = A3;
        e0.u = B0; e1.u = B1; e2.u = B2; e3.u = B3;
        if (kh > 0) {
            float* pA = &sh_p[((kh - 1) * 256 + u * 64 + b0) * 4];
            float* pB = &sh_p[((kh - 1) * 256 + u * 64 + b0 + 32) * 4];
            *(float4*)pA = make_float4(a0.f.x + a0.f.y, a1.f.x + a1.f.y,
                                       a2.f.x + a2.f.y, a3.f.x + a3.f.y);
            *(float4*)pB = make_float4(e0.f.x + e0.f.y, e1.f.x + e1.f.y,
                                       e2.f.x + e2.f.y, e3.f.x + e3.f.y);
        }
        __syncthreads();

        if (kh == 0) {
            float4 zA = make_float4(a0.f.x + a0.f.y + xgA.x, a1.f.x + a1.f.y + xgA.y,
                                    a2.f.x + a2.f.y + xgA.z, a3.f.x + a3.f.y + xgA.w);
            float4 zB = make_float4(e0.f.x + e0.f.y + xgB.x, e1.f.x + e1.f.y + xgB.y,
                                    e2.f.x + e2.f.y + xgB.z, e3.f.x + e3.f.y + xgB.w);
#pragma unroll
            for (int q = 1; q < 4; q++) {
                float4 pA = *(const float4*)&sh_p[((q - 1) * 256 + u * 64 + b0) * 4];
                float4 pB = *(const float4*)&sh_p[((q - 1) * 256 + u * 64 + b0 + 32) * 4];
                zA.x += pA.x; zA.y += pA.y; zA.z += pA.z; zA.w += pA.w;
                zB.x += pB.x; zB.y += pB.y; zB.z += pB.z; zB.w += pB.w;
            }
            float siA = 1.f / (1.f + expf(-zA.x));
            float sfA = 1.f / (1.f + expf(-zA.y));
            float soA = 1.f / (1.f + expf(-zA.w));
            float cnA = sfA * cA + siA * tanhf(zA.z);
            float hnA = soA * tanhf(cnA);
            cA = cnA;
            float siB = 1.f / (1.f + expf(-zB.x));
            float sfB = 1.f / (1.f + expf(-zB.y));
            float soB = 1.f / (1.f + expf(-zB.w));
            float cnB = sfB * cB + siB * tanhf(zB.z);
            float hnB = soB * tanhf(cnB);
            cB = cnB;
            float* hop = g_h + (size_t)(pout * 2 + dir) * 64 * 256;
            __stcg(&hop[b0 * 256 + hu], hnA);
            __stcg(&hop[(b0 + 32) * 256 + hu], hnB);
            sh_o[(t & 7) * 256 + (b0 << 2) + u] = hnA;
            sh_o[(t & 7) * 256 + ((b0 + 32) << 2) + u] = hnB;
        }

        gbar_arrive(ctr);
        if (kh == 0) {
            if ((t & 7) == 7) {
                int tbase = t & ~7;
#pragma unroll
                for (int j = 0; j < 8; j++) {
                    int ta = tbase + j;
                    int tta = dir ? (Tl - 1 - ta) : ta;
                    out[((size_t)b0 * Tl + tta) * 512 + dir * 256 + hu] =
                        sh_o[j * 256 + (b0 << 2) + u];
                    out[((size_t)(b0 + 32) * Tl + tta) * 512 + dir * 256 + hu] =
                        sh_o[j * 256 + ((b0 + 32) << 2) + u];
                }
            }
            if (t + 1 < Tl) {
                int tn = dir ? (Tl - 2 - t) : (t + 1);
                xgA = __ldg((const float4*)&xw[((size_t)b0 * Tl + tn) * 1024 + (hu << 2)]);
                xgB = __ldg((const float4*)&xw[((size_t)(b0 + 32) * Tl + tn) * 1024 + (hu << 2)]);
            }
        }
        gbar_wait(ctr, epoch, nb);
    }
    if (kh == 0) {
        g_c[(size_t)(dir * 64 + b0) * 256 + hu] = cA;
        g_c[(size_t)(dir * 64 + b0 + 32) * 256 + hu] = cB;
    }
}

// ---------------- persistent decoder: 512 threads, 2-way k-split ----------
// warps 16: kh = wrp>>3 (half of each 512-chunk), u = (wrp>>1)&3, bh = wrp&1.
#define DEC_SMEM ((16 * 1032 + 64 * 516 + 512 + 128 + 256 + 512 + 64 + 256 + 1024) * 4)
__global__ __launch_bounds__(512) void dec_scan(
    const float* __restrict__ sWih, const float* __restrict__ sWhh,
    const float* __restrict__ sb, const int* __restrict__ gt,
    const float* __restrict__ phi_b,
    const float* __restrict__ fcW, const float* __restrict__ fcb,
    float* __restrict__ out_lps)
{
    extern __shared__ float smem[];
    float* sh_w  = smem;                  // 16 x 1024 (pitch 1032)
    float* sh_x  = sh_w + 16 * 1032;      // 64 x 512 (pitch 516)
    float* sh_h  = sh_x + 64 * 516;       // 512
    float* sh_q  = sh_h + 512;            // 128
    float* sh_e  = sh_q + 128;            // 256
    float* sh_c2 = sh_e + 256;            // 512
    float* sh_l  = sh_c2 + 512;           // 64
    float* sr    = sh_l + 64;             // 256
    float* sh_p  = sr + 256;              // 256 x 4 partials

    int tid = threadIdx.x;
    int lane = tid & 31, wrp = tid >> 5;
    int kh = wrp >> 3;
    int u = (wrp >> 1) & 3;
    int bh = wrp & 1;
    int b = bh * 32 + lane;
    int hu0 = blockIdx.x << 2;
    int hu = hu0 + u;
    unsigned epoch = 0;
    const unsigned nb = gridDim.x;
    unsigned* ctr = &g_barD;

    for (int i = tid; i < 16 * 256; i += 512) {
        int r = i >> 8, kq = (i & 255) << 2;
        int grow = (r >> 2) * SHID + hu0 + (r & 3);
        float4 v;
        if (kq < 512) v = *(const float4*)&sWih[(size_t)grow * 560 + 48 + kq];
        else          v = *(const float4*)&sWhh[(size_t)grow * 512 + (kq - 512)];
        *(float4*)&sh_w[r * 1032 + kq] = v;
    }

    float creg = 0.f;
    float bi0 = 0.f, bi1 = 0.f, bi2 = 0.f, bi3 = 0.f;
    if (kh == 0) {
        __stcg(&g_dh[(size_t)b * 512 + hu], 0.f);
        __stcg(&g_ctx[(size_t)b * 512 + hu], __ldg(&g_feats[(size_t)b * 256 * 512 + hu]));
        bi0 = sb[0 * SHID + hu]; bi1 = sb[1 * SHID + hu];
        bi2 = sb[2 * SHID + hu]; bi3 = sb[3 * SHID + hu];
    }
    gbar(ctr, epoch, nb);

    const float* hp = &sh_x[b * 516 + kh * 256];
    float* pp = &sh_p[(u * 64 + b) * 4];

    for (int t = 0; t < TDEC; t++) {
        int pin = t & 1, pout = pin ^ 1;
        ull A0 = 0ull, A1 = 0ull, A2 = 0ull, A3 = 0ull;
        float x0 = 0.f, x1 = 0.f, x2 = 0.f, x3 = 0.f;
        if (kh == 0) {
            int tok = (t == 0) ? 0 : gt[b * TDEC + (t - 1)];
            x0 = sWih[(size_t)(0 * SHID + hu) * 560 + tok] + bi0;
            x1 = sWih[(size_t)(1 * SHID + hu) * 560 + tok] + bi1;
            x2 = sWih[(size_t)(2 * SHID + hu) * 560 + tok] + bi2;
            x3 = sWih[(size_t)(3 * SHID + hu) * 560 + tok] + bi3;
        }

        const float* hin = g_dh + (size_t)pin * 64 * 512;
#pragma unroll
        for (int c = 0; c < 2; c++) {
            __syncthreads();
            const float* src = (c == 0) ? g_ctx : hin;
            for (int i = tid; i < 8192; i += 512) {
                int bb = i >> 7, kq = (i & 127) << 2;
                *(float4*)&sh_x[bb * 516 + kq] = __ldcg((const float4*)&src[(size_t)bb * 512 + kq]);
            }
            __syncthreads();
            int wbase = c * 512 + kh * 256;
            const float* w0p = &sh_w[(0 * 4 + u) * 1032 + wbase];
            const float* w1p = &sh_w[(1 * 4 + u) * 1032 + wbase];
            const float* w2p = &sh_w[(2 * 4 + u) * 1032 + wbase];
            const float* w3p = &sh_w[(3 * 4 + u) * 1032 + wbase];
#pragma unroll 8
            for (int kk = 0; kk < 256; kk += 4) {
                UP h, w0, w1, w2, w3;
                h.f  = *(const float4*)&hp[kk];
                w0.f = *(const float4*)&w0p[kk];
                w1.f = *(const float4*)&w1p[kk];
                w2.f = *(const float4*)&w2p[kk];
                w3.f = *(const float4*)&w3p[kk];
                fma2(A0, h.u[0], w0.u[0]); fma2(A1, h.u[0], w1.u[0]);
                fma2(A2, h.u[0], w2.u[0]); fma2(A3, h.u[0], w3.u[0]);
                fma2(A0, h.u[1], w0.u[1]); fma2(A1, h.u[1], w1.u[1]);
                fma2(A2, h.u[1], w2.u[1]); fma2(A3, h.u[1], w3.u[1]);
            }
        }
        U2 r0, r1, r2, r3;
        r0.u = A0; r1.u = A1; r2.u = A2; r3.u = A3;
        if (kh == 1) {
            *(float4*)pp = make_float4(r0.f.x + r0.f.y, r1.f.x + r1.f.y,
                                       r2.f.x + r2.f.y, r3.f.x + r3.f.y);
        }
        __syncthreads();
        if (kh == 0) {
            float4 p = *(const float4*)pp;
            float acc0 = r0.f.x + r0.f.y + p.x + x0;
            float acc1 = r1.f.x + r1.f.y + p.y + x1;
            float acc2 = r2.f.x + r2.f.y + p.z + x2;
            float acc3 = r3.f.x + r3.f.y + p.w + x3;
            float si = 1.f / (1.f + expf(-acc0));
            float sf = 1.f / (1.f + expf(-acc1));
            float so = 1.f / (1.f + expf(-acc3));
            float cn = sf * creg + si * tanhf(acc2);
            float hn = so * tanhf(cn);
            creg = cn;
            __stcg(&g_dh[(size_t)pout * 64 * 512 + b * 512 + hu], hn);
        }
        gbar(ctr, epoch, nb);

        // -------- attention / logits: blocks 0..63, one per batch row --------
        if (blockIdx.x < 64) {
            int bb = blockIdx.x;
            const float* h = g_dh + (size_t)pout * 64 * 512 + (size_t)bb * 512;
            sh_h[tid] = __ldcg(&h[tid]);          // 512 threads = 512 dims
            __syncthreads();

            if (tid < 256) {
                int j = tid >> 1, hf = tid & 1;
                const float* pw = g_phiWt + (size_t)hf * 256 * 128;
                const float* hh = sh_h + hf * 256;
                float a0 = 0.f, a1 = 0.f, a2 = 0.f, a3 = 0.f;
                for (int k = 0; k < 256; k += 4) {
                    a0 += hh[k + 0] * pw[(k + 0) * 128 + j];
                    a1 += hh[k + 1] * pw[(k + 1) * 128 + j];
                    a2 += hh[k + 2] * pw[(k + 2) * 128 + j];
                    a3 += hh[k + 3] * pw[(k + 3) * 128 + j];
                }
                sr[tid] = a0 + a1 + a2 + a3;
            }
            __syncthreads();
            if (tid < 128) {
                float q = sr[2 * tid] + sr[2 * tid + 1] + phi_b[tid];
                sh_q[tid] = q > 0.f ? q : 0.f;
            }
            __syncthreads();

            if (tid < 256) {
                const float* cfp = g_cf + ((size_t)bb * 256 + tid) * 128;
                float a0 = 0.f, a1 = 0.f, a2 = 0.f, a3 = 0.f;
                for (int j = 0; j < 128; j += 4) {
                    a0 += sh_q[j + 0] * cfp[j + 0];
                    a1 += sh_q[j + 1] * cfp[j + 1];
                    a2 += sh_q[j + 2] * cfp[j + 2];
                    a3 += sh_q[j + 3] * cfp[j + 3];
                }
                sh_e[tid] = a0 + a1 + a2 + a3;
            }
            __syncthreads();

            if (tid < 256) sr[tid] = sh_e[tid];
            __syncthreads();
            for (int s = 128; s > 0; s >>= 1) {
                if (tid < s) sr[tid] = fmaxf(sr[tid], sr[tid + s]);
                __syncthreads();
            }
            float m = sr[0];
            __syncthreads();
            float e = 0.f;
            if (tid < 256) { e = expf(sh_e[tid] - m); sr[tid] = e; }
            __syncthreads();
            for (int s = 128; s > 0; s >>= 1) {
                if (tid < s) sr[tid] += sr[tid + s];
                __syncthreads();
            }
            float inv = 1.f / sr[0];
            __syncthreads();
            if (tid < 256) sh_e[tid] = e * inv;
            __syncthreads();

            {
                int d = tid;  // 512 threads = 512 dims
                const float* fp = g_feats + (size_t)bb * 256 * 512 + d;
                float a0 = 0.f, a1 = 0.f, a2 = 0.f, a3 = 0.f;
                for (int tt2 = 0; tt2 < 256; tt2 += 4) {
                    a0 += sh_e[tt2 + 0] * fp[(size_t)(tt2 + 0) * 512];
                    a1 += sh_e[tt2 + 1] * fp[(size_t)(tt2 + 1) * 512];
                    a2 += sh_e[tt2 + 2] * fp[(size_t)(tt2 + 2) * 512];
                    a3 += sh_e[tt2 + 3] * fp[(size_t)(tt2 + 3) * 512];
                }
                float cv = a0 + a1 + a2 + a3;
                sh_c2[d] = cv;
                __stcg(&g_ctx[(size_t)bb * 512 + d], cv);
            }
            __syncthreads();

            if (tid < 192) {
                int v2 = tid >> 2, part = tid & 3;
                const float* wr = fcW + (size_t)v2 * 1024 + part * 256;
                const float* src = (part < 2) ? (sh_h + part * 256) : (sh_c2 + (part - 2) * 256);
                float a0 = 0.f, a1 = 0.f, a2 = 0.f, a3 = 0.f;
                for (int k = 0; k < 256; k += 4) {
                    a0 += src[k + 0] * wr[k + 0];
                    a1 += src[k + 1] * wr[k + 1];
                    a2 += src[k + 2] * wr[k + 2];
                    a3 += src[k + 3] * wr[k + 3];
                }
                sr[tid] = a0 + a1 + a2 + a3;
            }
            __syncthreads();
            if (tid < 48) {
                sh_l[tid] = sr[tid * 4] + sr[tid * 4 + 1] + sr[tid * 4 + 2] + sr[tid * 4 + 3] + fcb[tid];
            }
            __syncthreads();
            if (tid < 48) {
                float m2 = -1e30f;
                for (int j = 0; j < 48; j++) m2 = fmaxf(m2, sh_l[j]);
                float s2 = 0.f;
                for (int j = 0; j < 48; j++) s2 += expf(sh_l[j] - m2);
                out_lps[(size_t)bb * TDEC * NVOC + (size_t)t * NVOC + tid] = sh_l[tid] - m2 - logf(s2);
            }
        }
        gbar(ctr, epoch, nb);
    }
}

// ---------------- small helpers ----------------
__global__ void transpose_phi(const float* __restrict__ W) {
    int j = blockIdx.x;
    for (int k = threadIdx.x; k < 512; k += 256) g_phiWt[k * 128 + j] = W[j * 512 + k];
}

__global__ void fin_hc(float* __restrict__ out) {
    int b = blockIdx.x;
    for (int i = threadIdx.x; i < 1024; i += 256) {
        int q = i >> 8, r = i & 255;
        float v;
        if (q == 0)      v = g_h[(size_t)(0 * 2 + 0) * 64 * 256 + b * 256 + r];
        else if (q == 1) v = g_h[(size_t)(0 * 2 + 1) * 64 * 256 + b * 256 + r];
        else if (q == 2) v = g_c[(size_t)(0 * 64 + b) * 256 + r];
        else             v = g_c[(size_t)(1 * 64 + b) * 256 + r];
        out[(size_t)b * 1024 + i] = v;
    }
}

// ---------------- host launcher ----------------
extern "C" void kernel_launch(void* const* d_in, const int* in_sizes, int n_in,
                              void* d_out, int out_size)
{
    const float* inputs = (const float*)d_in[0];
    const int*   gt     = (const int*)d_in[1];
    const float* W[27];
    for (int i = 0; i < 27; i++) W[i] = (const float*)d_in[i + 2];

    float *xw0, *xw1, *out0, *out1, *feats, *cf;
    cudaGetSymbolAddress((void**)&xw0, g_xw0);
    cudaGetSymbolAddress((void**)&xw1, g_xw1);
    cudaGetSymbolAddress((void**)&out0, g_out0);
    cudaGetSymbolAddress((void**)&out1, g_out1);
    cudaGetSymbolAddress((void**)&feats, g_feats);
    cudaGetSymbolAddress((void**)&cf, g_cf);

    cudaFuncSetAttribute(enc_scan, cudaFuncAttributeMaxDynamicSharedMemorySize, ENC_SMEM);
    cudaFuncSetAttribute(dec_scan, cudaFuncAttributeMaxDynamicSharedMemorySize, DEC_SMEM);

    float* dout = (float*)d_out;

    const float* A = inputs;
    float* outs[3] = {out0, out1, feats};
    int Tl = 1024, K = 160;
    unsigned ebase = 0;
    for (int l = 0; l < 3; l++) {
        int M = 64 * Tl;
        dim3 gg(1024 / 64, M / 128);
        gemm_bias<<<gg, 256>>>(A, W[l * 6 + 0], W[l * 6 + 2], xw0, M, 1024, K, 0, 1);
        gemm_bias<<<gg, 256>>>(A, W[l * 6 + 3], W[l * 6 + 5], xw1, M, 1024, K, 0, 1);
        if (l == 0) reset_bars<<<1, 32>>>();
        enc_scan<<<dim3(64, 2), 512, ENC_SMEM>>>(xw0, xw1, W[l * 6 + 1], W[l * 6 + 4],
                                                 outs[l], Tl, ebase);
        ebase += 64u * (unsigned)(Tl + 1);
        A = outs[l];
        Tl >>= 1;
        K = 1024;
    }

    // comp_feat = relu(feats @ psi_W^T + psi_b)   [16384,128]
    gemm_bias<<<dim3(2, 16384 / 128), 256>>>(feats, W[23], W[24], cf, 16384, 128, 512, 1, 0);
    transpose_phi<<<128, 256>>>(W[21]);
    fin_hc<<<64, 256>>>(dout + (size_t)BATCH * TDEC * NVOC);

    // ---------------- decoder ----------------
    dec_scan<<<128, 512, DEC_SMEM>>>(W[18], W[19], W[20], gt, W[22], W[25], W[26], dout);
}